// round 5
// baseline (speedup 1.0000x reference)
#include <cuda_runtime.h>
#include <cuda_bf16.h>
#include <math.h>
#include <float.h>

#define BGR   32
#define NPER0 1024
#define N0    (BGR * NPER0)
#define HID   128
#define NE    524288
#define KK1   512
#define KK2   256
#define KK3   128
#define NC    10
#define MAXDEG 128
#define N1    (BGR * KK1)
#define N2    (BGR * KK2)

// ---------------- scratch (static device memory) ----------------
__device__ __align__(16) float g_X[N0 * HID];
__device__ __align__(16) float g_X2[N0 * HID];
__device__ float g_dinv[N0];
__device__ float g_deginv[N0];
__device__ float g_cat4[N0 * 4];
__device__ int   g_nmap[N0];
__device__ int   g_cnt0[N0];
__device__ int   g_cnt1[N1];
__device__ int   g_cnt2[N2];
__device__ int   g_csr[N0 * MAXDEG];
__device__ int   g_srcA[NE], g_dstA[NE];
__device__ int   g_srcB[NE], g_dstB[NE];
__device__ int   g_ecnt[2];
__device__ float g_r[BGR * 2 * HID];

static inline int ceil_div(int a, int b) { return (a + b - 1) / b; }

// ---------------- kernels ----------------
__global__ void k_init(int* c0, int* c1, int* c2, int* ecnt) {
    int i = blockIdx.x * blockDim.x + threadIdx.x;
    if (i < N0) c0[i] = 0;
    if (i < N1) c1[i] = 0;
    if (i < N2) c2[i] = 0;
    if (i < 2)  ecnt[i] = 0;
}

__global__ void k_build(const int* __restrict__ src, const int* __restrict__ dst,
                        int* __restrict__ cnt, int* __restrict__ csr,
                        const int* __restrict__ cntp, int cntv) {
    int n = cntp ? *cntp : cntv;
    int e = blockIdx.x * blockDim.x + threadIdx.x;
    if (e >= n) return;
    int d = dst[e];
    int slot = atomicAdd(&cnt[d], 1);
    if (slot < MAXDEG) csr[d * MAXDEG + slot] = src[e];
}

__global__ void k_dinv(const int* __restrict__ cnt, float* __restrict__ dinv,
                       float* __restrict__ deginv, int n) {
    int i = blockIdx.x * blockDim.x + threadIdx.x;
    if (i >= n) return;
    float deg = (float)(cnt[i] + 1);
    dinv[i] = rsqrtf(deg);
    deginv[i] = 1.0f / deg;
}

// Barrier-free fused agg + per-head projection + relu + attention partials.
// Block = 256 threads (8 warps), W in smem. Each warp independently processes
// (node, head) pairs: head h's inputs/outputs are features [32h, 32h+32) which
// live wholly inside one warp (block-diagonal W) -> no cross-warp traffic.
// catp partial per head -> cat4[node*4+head] (unique slot, no atomics).
#define NPB2 16
__global__ void k_aggXP(const float* __restrict__ Xin, const int* __restrict__ cnt,
                        const int* __restrict__ csr, const float* __restrict__ dinv,
                        const float* __restrict__ deginv, const float* __restrict__ W,
                        const float* __restrict__ b, const float* __restrict__ A,
                        const float* __restrict__ psW,
                        float* __restrict__ Xout, float* __restrict__ cat4, int n) {
    __shared__ float sW[4096];
    int t = threadIdx.x;
    for (int i = t; i < 4096; i += 256) sW[i] = W[i];
    __syncthreads();
    int w = t >> 5, lane = t & 31;
    int base = blockIdx.x * NPB2;
    #pragma unroll 1
    for (int p = w; p < NPB2 * 4; p += 8) {
        int node = base + (p >> 2);
        int head = p & 3;
        if (node >= n) break;
        int fb = head * 32 + lane;
        int deg = cnt[node];
        float di = dinv[node], g2 = deginv[node];
        const int* row = csr + (size_t)node * MAXDEG;
        float a0 = 0.f, a1 = 0.f, a2 = 0.f, a3 = 0.f;
        int j = 0;
        for (; j + 4 <= deg; j += 4) {
            int s0 = row[j], s1 = row[j+1], s2 = row[j+2], s3 = row[j+3];
            float c0 = dinv[s0], c1 = dinv[s1], c2 = dinv[s2], c3 = dinv[s3];
            a0 = fmaf(Xin[(size_t)s0 * 128 + fb], c0, a0);
            a1 = fmaf(Xin[(size_t)s1 * 128 + fb], c1, a1);
            a2 = fmaf(Xin[(size_t)s2 * 128 + fb], c2, a2);
            a3 = fmaf(Xin[(size_t)s3 * 128 + fb], c3, a3);
        }
        for (; j < deg; j++) {
            int s = row[j];
            a0 = fmaf(Xin[(size_t)s * 128 + fb], dinv[s], a0);
        }
        float acc = (a0 + a1) + (a2 + a3);
        float v = fmaf(acc, di, Xin[(size_t)node * 128 + fb] * g2);
        // per-head projection via shuffle broadcast + smem W
        const float* wh = sW + head * 1024;
        float o = 0.f;
        #pragma unroll
        for (int d = 0; d < 32; d++)
            o = fmaf(__shfl_sync(0xffffffffu, v, d), wh[d * 32 + lane], o);
        o = fmaxf(o + b[fb], 0.f);
        Xout[(size_t)node * 128 + fb] = o;
        float att = o * A[fb];
        #pragma unroll
        for (int ofs = 16; ofs > 0; ofs >>= 1)
            att += __shfl_xor_sync(0xffffffffu, att, ofs);
        float cp = att * o * psW[fb];
        #pragma unroll
        for (int ofs = 16; ofs > 0; ofs >>= 1)
            cp += __shfl_xor_sync(0xffffffffu, cp, ofs);
        if (lane == 0) cat4[node * 4 + head] = cp;
    }
}

// Fused per-graph: cat4 reduce -> smem catd, score gather (smem), bitonic sort,
// nmap, pool + readout.  score = (sum_nbr catd + catd_self)*dinv + psb
// (since catself = catp*deginv = catp*dinv*dinv = catd*dinv).
__global__ void k_select(const float* __restrict__ cat4, const float* __restrict__ dinv,
                         const int* __restrict__ cnt, const int* __restrict__ csr,
                         const float* __restrict__ psb, const float* __restrict__ Xmid,
                         int* __restrict__ nmap, float* __restrict__ Xpool,
                         float* __restrict__ r, int nper, int k, int accum) {
    __shared__ float sk[1024];
    __shared__ int   si[1024];
    __shared__ float scd[1024];
    __shared__ float smx[512], ssm[512];
    int g = blockIdx.x, t = threadIdx.x;   // 512 threads
    int base = g * nper;
    for (int i = t; i < nper; i += 512) {
        int node = base + i;
        const float4 c4 = ((const float4*)cat4)[node];
        scd[i] = (c4.x + c4.y + c4.z + c4.w) * dinv[node];
        nmap[node] = -1;
    }
    __syncthreads();
    float pb = psb[0];
    for (int i = t; i < nper; i += 512) {
        int node = base + i;
        int deg = cnt[node];
        const int* row = csr + (size_t)node * MAXDEG;
        float acc = scd[i] * dinv[node];   // self term: catd*dinv
        float s2 = 0.f;
        for (int j = 0; j < deg; j++) s2 += scd[row[j] - base];
        sk[i] = fmaf(s2, dinv[node], acc) + pb;
        si[i] = i;
    }
    __syncthreads();
    for (int ks = 2; ks <= nper; ks <<= 1) {
        for (int j = ks >> 1; j > 0; j >>= 1) {
            for (int i = t; i < nper; i += 512) {
                int ixj = i ^ j;
                if (ixj > i) {
                    float ka = sk[i], kb = sk[ixj];
                    int ia = si[i], ib = si[ixj];
                    bool a_before_b = (ka > kb) || (ka == kb && ia < ib);
                    bool dirUp = ((i & ks) == 0);
                    bool sw = dirUp ? (!a_before_b) : a_before_b;
                    if (sw) { sk[i] = kb; sk[ixj] = ka; si[i] = ib; si[ixj] = ia; }
                }
            }
            __syncthreads();
        }
    }
    for (int jj = t; jj < k; jj += 512) nmap[base + si[jj]] = g * k + jj;
    int f = t & 127, c = t >> 7;
    float mx = -FLT_MAX, sm = 0.f;
    for (int j = c; j < k; j += 4) {
        int orig = base + si[j];
        float tv = tanhf(sk[j]);
        float v = Xmid[(size_t)orig * 128 + f] * tv;
        Xpool[(size_t)(g * k + j) * 128 + f] = v;
        mx = fmaxf(mx, v);
        sm += v;
    }
    smx[t] = mx; ssm[t] = sm;
    __syncthreads();
    if (c == 0) {
        #pragma unroll
        for (int cc = 1; cc < 4; cc++) {
            mx = fmaxf(mx, smx[cc * 128 + f]);
            sm += ssm[cc * 128 + f];
        }
        float o1 = mx, o2 = sm / (float)k;
        if (accum) { r[g * 256 + f] += o1; r[g * 256 + 128 + f] += o2; }
        else       { r[g * 256 + f]  = o1; r[g * 256 + 128 + f]  = o2; }
    }
}

__global__ void k_compact(const int* __restrict__ srcI, const int* __restrict__ dstI,
                          const int* __restrict__ nmap, int* __restrict__ srcO,
                          int* __restrict__ dstO, int* __restrict__ cntOut,
                          const int* __restrict__ cntp, int cntv) {
    int n = cntp ? *cntp : cntv;
    int e = blockIdx.x * blockDim.x + threadIdx.x;
    if (e >= n) return;
    int ns = nmap[srcI[e]], nd = nmap[dstI[e]];
    if (ns >= 0 && nd >= 0) {
        int p = atomicAdd(cntOut, 1);
        srcO[p] = ns;
        dstO[p] = nd;
    }
}

__global__ void k_mlp(const float* __restrict__ r,
                      const float* __restrict__ l1W, const float* __restrict__ l1b,
                      const float* __restrict__ l2W, const float* __restrict__ l2b,
                      const float* __restrict__ l3W, const float* __restrict__ l3b,
                      float* __restrict__ out) {
    __shared__ float z0[256], z1[128], z2[64], z3[16];
    __shared__ float red2[2];
    int g = blockIdx.x, t = threadIdx.x;
    z0[t] = r[g * 256 + t];
    z0[t + 128] = r[g * 256 + 128 + t];
    __syncthreads();
    {
        float acc = l1b[t];
        for (int i = 0; i < 256; i++) acc = fmaf(z0[i], l1W[i * 128 + t], acc);
        z1[t] = fmaxf(acc, 0.f);
    }
    __syncthreads();
    if (t < 64) {
        float acc = l2b[t];
        for (int i = 0; i < 128; i++) acc = fmaf(z1[i], l2W[i * 64 + t], acc);
        z2[t] = fmaxf(acc, 0.f);
    }
    __syncthreads();
    if (t < NC) {
        float acc = l3b[t];
        for (int i = 0; i < 64; i++) acc = fmaf(z2[i], l3W[i * NC + t], acc);
        z3[t] = acc;
    }
    __syncthreads();
    if (t == 0) {
        float m = -FLT_MAX;
        for (int c = 0; c < NC; c++) m = fmaxf(m, z3[c]);
        float s = 0.f;
        for (int c = 0; c < NC; c++) s += expf(z3[c] - m);
        red2[0] = m; red2[1] = logf(s);
    }
    __syncthreads();
    if (t < NC) out[g * NC + t] = z3[t] - red2[0] - red2[1];
}

// ---------------- host side ----------------
struct Ptrs {
    float *X, *X2, *dinv, *deginv, *cat4, *r;
    int *nmap, *cnt0, *cnt1, *cnt2, *csr;
    int *srcA, *dstA, *srcB, *dstB, *ecnt;
};

static void run_stage(const Ptrs& P, const float* Xin, int* cnt, int n, int k,
                      const int* src, const int* dst, const int* cntp,
                      const float* W, const float* b, const float* A,
                      const float* psW, const float* psb,
                      float* Xpool, int accum,
                      bool doCompact, int* srcO, int* dstO, int* cntOut) {
    int nper = n / BGR;
    int egrid = ceil_div(NE, 256);
    k_build<<<egrid, 256>>>(src, dst, cnt, P.csr, cntp, NE);
    k_dinv<<<ceil_div(n, 256), 256>>>(cnt, P.dinv, P.deginv, n);
    k_aggXP<<<ceil_div(n, NPB2), 256>>>(Xin, cnt, P.csr, P.dinv, P.deginv,
                                        W, b, A, psW, P.X, P.cat4, n);
    k_select<<<BGR, 512>>>(P.cat4, P.dinv, cnt, P.csr, psb,
                           P.X, P.nmap, Xpool, P.r, nper, k, accum);
    if (doCompact)
        k_compact<<<egrid, 256>>>(src, dst, P.nmap, srcO, dstO, cntOut, cntp, NE);
}

extern "C" void kernel_launch(void* const* d_in, const int* in_sizes, int n_in,
                              void* d_out, int out_size) {
    const float* x   = (const float*)d_in[0];
    const int*   src = (const int*)d_in[1];
    const int*   dst = (const int*)d_in[2];
    const float* W1 = (const float*)d_in[3];
    const float* b1 = (const float*)d_in[4];
    const float* A1 = (const float*)d_in[5];
    const float* ps1W = (const float*)d_in[6];
    const float* ps1b = (const float*)d_in[7];
    const float* W2 = (const float*)d_in[8];
    const float* b2 = (const float*)d_in[9];
    const float* A2 = (const float*)d_in[10];
    const float* ps2W = (const float*)d_in[11];
    const float* ps2b = (const float*)d_in[12];
    const float* W3 = (const float*)d_in[13];
    const float* b3 = (const float*)d_in[14];
    const float* A3 = (const float*)d_in[15];
    const float* ps3W = (const float*)d_in[16];
    const float* ps3b = (const float*)d_in[17];
    const float* l1W = (const float*)d_in[18];
    const float* l1b = (const float*)d_in[19];
    const float* l2W = (const float*)d_in[20];
    const float* l2b = (const float*)d_in[21];
    const float* l3W = (const float*)d_in[22];
    const float* l3b = (const float*)d_in[23];
    float* out = (float*)d_out;

    Ptrs P;
    cudaGetSymbolAddress((void**)&P.X, g_X);
    cudaGetSymbolAddress((void**)&P.X2, g_X2);
    cudaGetSymbolAddress((void**)&P.dinv, g_dinv);
    cudaGetSymbolAddress((void**)&P.deginv, g_deginv);
    cudaGetSymbolAddress((void**)&P.cat4, g_cat4);
    cudaGetSymbolAddress((void**)&P.r, g_r);
    cudaGetSymbolAddress((void**)&P.nmap, g_nmap);
    cudaGetSymbolAddress((void**)&P.cnt0, g_cnt0);
    cudaGetSymbolAddress((void**)&P.cnt1, g_cnt1);
    cudaGetSymbolAddress((void**)&P.cnt2, g_cnt2);
    cudaGetSymbolAddress((void**)&P.csr, g_csr);
    cudaGetSymbolAddress((void**)&P.srcA, g_srcA);
    cudaGetSymbolAddress((void**)&P.dstA, g_dstA);
    cudaGetSymbolAddress((void**)&P.srcB, g_srcB);
    cudaGetSymbolAddress((void**)&P.dstB, g_dstB);
    cudaGetSymbolAddress((void**)&P.ecnt, g_ecnt);

    k_init<<<ceil_div(N0, 256), 256>>>(P.cnt0, P.cnt1, P.cnt2, P.ecnt);

    run_stage(P, x, P.cnt0, N0, KK1, src, dst, nullptr,
              W1, b1, A1, ps1W, ps1b, P.X2, 0,
              true, P.srcA, P.dstA, &P.ecnt[0]);
    run_stage(P, P.X2, P.cnt1, N1, KK2, P.srcA, P.dstA, &P.ecnt[0],
              W2, b2, A2, ps2W, ps2b, P.X2, 1,
              true, P.srcB, P.dstB, &P.ecnt[1]);
    run_stage(P, P.X2, P.cnt2, N2, KK3, P.srcB, P.dstB, &P.ecnt[1],
              W3, b3, A3, ps3W, ps3b, P.X2, 1,
              false, nullptr, nullptr, nullptr);

    k_mlp<<<BGR, 128>>>(P.r, l1W, l1b, l2W, l2b, l3W, l3b, out);
}

// round 6
// speedup vs baseline: 1.3437x; 1.3437x over previous
#include <cuda_runtime.h>
#include <cuda_bf16.h>
#include <math.h>
#include <float.h>

#define BGR   32
#define NPER0 1024
#define N0    (BGR * NPER0)
#define HID   128
#define NE    524288
#define KK1   512
#define KK2   256
#define KK3   128
#define NC    10
#define MAXDEG 128
#define N1    (BGR * KK1)
#define N2    (BGR * KK2)

// ---------------- scratch (static device memory) ----------------
__device__ __align__(16) float g_X[N0 * HID];    // post-layer output
__device__ __align__(16) float g_X2[N0 * HID];   // pooled features (stage input)
__device__ __align__(16) float g_XS[N0 * HID];   // Xin * dinv (pre-scaled)
__device__ float g_dinv[N0];
__device__ float g_catd[N0];
__device__ int   g_nmap[N0];
__device__ int   g_cnt0[N0];
__device__ int   g_cnt1[N1];
__device__ int   g_cnt2[N2];
__device__ int   g_csr[N0 * MAXDEG];
__device__ int   g_srcA[NE], g_dstA[NE];
__device__ int   g_srcB[NE], g_dstB[NE];
__device__ int   g_ecnt[2];
__device__ float g_r[BGR * 2 * HID];

static inline int ceil_div(int a, int b) { return (a + b - 1) / b; }

// ---------------- kernels ----------------
__global__ void k_init(int* c0, int* c1, int* c2, int* ecnt) {
    int i = blockIdx.x * blockDim.x + threadIdx.x;
    if (i < N0) c0[i] = 0;
    if (i < N1) c1[i] = 0;
    if (i < N2) c2[i] = 0;
    if (i < 2)  ecnt[i] = 0;
}

__global__ void k_build(const int* __restrict__ src, const int* __restrict__ dst,
                        int* __restrict__ cnt, int* __restrict__ csr,
                        const int* __restrict__ cntp, int cntv) {
    int n = cntp ? *cntp : cntv;
    int e = blockIdx.x * blockDim.x + threadIdx.x;
    if (e >= n) return;
    int d = dst[e];
    int slot = atomicAdd(&cnt[d], 1);
    if (slot < MAXDEG) csr[d * MAXDEG + slot] = src[e];
}

__global__ void k_dinv(const int* __restrict__ cnt, float* __restrict__ dinv, int n) {
    int i = blockIdx.x * blockDim.x + threadIdx.x;
    if (i >= n) return;
    dinv[i] = rsqrtf((float)(cnt[i] + 1));
}

// Xs = Xin * dinv[node]  (float4 elements; n*32 float4s)
__global__ void k_scale(const float* __restrict__ Xin, const float* __restrict__ dinv,
                        float* __restrict__ Xs, int n) {
    int i = blockIdx.x * blockDim.x + threadIdx.x;
    if (i >= n * 32) return;
    float4 v = ((const float4*)Xin)[i];
    float d = dinv[i >> 5];
    float4 o = make_float4(v.x * d, v.y * d, v.z * d, v.w * d);
    ((float4*)Xs)[i] = o;
}

// Warp-per-node fused kernel. Lane holds features [4*lane, 4*lane+4) (float4).
// agg: acc4 = sum_nbr Xs4[nbr] + Xs4[self];  v = acc4 * dinv[node]
// proj: head = lane/8 (block-diagonal W); 8x float4 shuffle broadcast + smem W
// epilogue: bias+relu -> Xout; att per head; catp -> catd[node] = catp*dinv.
#define NPB3 32
__global__ void k_aggXP(const float* __restrict__ Xs, const int* __restrict__ cnt,
                        const int* __restrict__ csr, const float* __restrict__ dinv,
                        const float* __restrict__ W, const float* __restrict__ b,
                        const float* __restrict__ A, const float* __restrict__ psW,
                        float* __restrict__ Xout, float* __restrict__ catd, int n) {
    __shared__ float sW[4096];
    int t = threadIdx.x;
    #pragma unroll
    for (int i = 0; i < 16; i++) sW[i * 256 + t] = W[i * 256 + t];
    __syncthreads();
    int w = t >> 5, lane = t & 31;
    int head = lane >> 3;
    int baseLane = head << 3;
    int oct = lane & 7;
    const float4* Xs4 = (const float4*)Xs;
    float4 b4  = ((const float4*)b)[lane];
    float4 A4  = ((const float4*)A)[lane];
    float4 pw4 = ((const float4*)psW)[lane];
    const float* whBase = sW + head * 1024 + oct * 4;
    int base = blockIdx.x * NPB3;
    #pragma unroll 1
    for (int it = 0; it < NPB3 / 8; it++) {
        int node = base + it * 8 + w;
        if (node >= n) break;
        int deg = cnt[node];
        float di = dinv[node];
        const int* row = csr + (size_t)node * MAXDEG;
        float4 acc = Xs4[(size_t)node * 32 + lane];   // self term
        int j = 0;
        for (; j + 4 <= deg; j += 4) {
            int4 s4 = *(const int4*)(row + j);
            float4 v0 = Xs4[(size_t)s4.x * 32 + lane];
            float4 v1 = Xs4[(size_t)s4.y * 32 + lane];
            float4 v2 = Xs4[(size_t)s4.z * 32 + lane];
            float4 v3 = Xs4[(size_t)s4.w * 32 + lane];
            acc.x += (v0.x + v1.x) + (v2.x + v3.x);
            acc.y += (v0.y + v1.y) + (v2.y + v3.y);
            acc.z += (v0.z + v1.z) + (v2.z + v3.z);
            acc.w += (v0.w + v1.w) + (v2.w + v3.w);
        }
        for (; j < deg; j++) {
            float4 v0 = Xs4[(size_t)row[j] * 32 + lane];
            acc.x += v0.x; acc.y += v0.y; acc.z += v0.z; acc.w += v0.w;
        }
        float4 v = make_float4(acc.x * di, acc.y * di, acc.z * di, acc.w * di);
        // projection: o[e] = sum_d v_head[d] * W[head][d][e]
        float4 o = make_float4(0.f, 0.f, 0.f, 0.f);
        #pragma unroll
        for (int i = 0; i < 8; i++) {
            int sl = baseLane + i;
            float vv0 = __shfl_sync(0xffffffffu, v.x, sl);
            float vv1 = __shfl_sync(0xffffffffu, v.y, sl);
            float vv2 = __shfl_sync(0xffffffffu, v.z, sl);
            float vv3 = __shfl_sync(0xffffffffu, v.w, sl);
            const float* wp = whBase + (i * 4) * 32;
            float4 w0 = *(const float4*)(wp);
            float4 w1 = *(const float4*)(wp + 32);
            float4 w2 = *(const float4*)(wp + 64);
            float4 w3 = *(const float4*)(wp + 96);
            o.x = fmaf(vv0, w0.x, o.x); o.y = fmaf(vv0, w0.y, o.y);
            o.z = fmaf(vv0, w0.z, o.z); o.w = fmaf(vv0, w0.w, o.w);
            o.x = fmaf(vv1, w1.x, o.x); o.y = fmaf(vv1, w1.y, o.y);
            o.z = fmaf(vv1, w1.z, o.z); o.w = fmaf(vv1, w1.w, o.w);
            o.x = fmaf(vv2, w2.x, o.x); o.y = fmaf(vv2, w2.y, o.y);
            o.z = fmaf(vv2, w2.z, o.z); o.w = fmaf(vv2, w2.w, o.w);
            o.x = fmaf(vv3, w3.x, o.x); o.y = fmaf(vv3, w3.y, o.y);
            o.z = fmaf(vv3, w3.z, o.z); o.w = fmaf(vv3, w3.w, o.w);
        }
        o.x = fmaxf(o.x + b4.x, 0.f);
        o.y = fmaxf(o.y + b4.y, 0.f);
        o.z = fmaxf(o.z + b4.z, 0.f);
        o.w = fmaxf(o.w + b4.w, 0.f);
        ((float4*)Xout)[(size_t)node * 32 + lane] = o;
        // att per head (reduce over octet)
        float att = o.x * A4.x + o.y * A4.y + o.z * A4.z + o.w * A4.w;
        att += __shfl_xor_sync(0xffffffffu, att, 1);
        att += __shfl_xor_sync(0xffffffffu, att, 2);
        att += __shfl_xor_sync(0xffffffffu, att, 4);
        // catp = sum_f att[head(f)] * o[f] * psW[f]  (full-warp reduce)
        float cp = att * (o.x * pw4.x + o.y * pw4.y + o.z * pw4.z + o.w * pw4.w);
        #pragma unroll
        for (int ofs = 16; ofs > 0; ofs >>= 1)
            cp += __shfl_xor_sync(0xffffffffu, cp, ofs);
        if (lane == 0) catd[node] = cp * di;
    }
}

// Fused per-graph: score gather (smem catd), bitonic sort, nmap, pool+readout.
// score = (sum_nbr catd + catd_self)*dinv + psb   (catself = catd*dinv)
__global__ void k_select(const float* __restrict__ catd, const float* __restrict__ dinv,
                         const int* __restrict__ cnt, const int* __restrict__ csr,
                         const float* __restrict__ psb, const float* __restrict__ Xmid,
                         int* __restrict__ nmap, float* __restrict__ Xpool,
                         float* __restrict__ r, int nper, int k, int accum) {
    __shared__ float sk[1024];
    __shared__ int   si[1024];
    __shared__ float scd[1024];
    __shared__ float smx[512], ssm[512];
    int g = blockIdx.x, t = threadIdx.x;   // 512 threads
    int base = g * nper;
    for (int i = t; i < nper; i += 512) {
        int node = base + i;
        scd[i] = catd[node];
        nmap[node] = -1;
    }
    __syncthreads();
    float pb = psb[0];
    for (int i = t; i < nper; i += 512) {
        int node = base + i;
        int deg = cnt[node];
        const int* row = csr + (size_t)node * MAXDEG;
        float din = dinv[node];
        float s2 = scd[i] * din;          // self term
        for (int j = 0; j < deg; j++) s2 += scd[row[j] - base];
        sk[i] = fmaf(s2, din, pb);
        si[i] = i;
    }
    __syncthreads();
    for (int ks = 2; ks <= nper; ks <<= 1) {
        for (int j = ks >> 1; j > 0; j >>= 1) {
            for (int i = t; i < nper; i += 512) {
                int ixj = i ^ j;
                if (ixj > i) {
                    float ka = sk[i], kb = sk[ixj];
                    int ia = si[i], ib = si[ixj];
                    bool a_before_b = (ka > kb) || (ka == kb && ia < ib);
                    bool dirUp = ((i & ks) == 0);
                    bool sw = dirUp ? (!a_before_b) : a_before_b;
                    if (sw) { sk[i] = kb; sk[ixj] = ka; si[i] = ib; si[ixj] = ia; }
                }
            }
            __syncthreads();
        }
    }
    for (int jj = t; jj < k; jj += 512) nmap[base + si[jj]] = g * k + jj;
    int f = t & 127, c = t >> 7;
    float mx = -FLT_MAX, sm = 0.f;
    for (int j = c; j < k; j += 4) {
        int orig = base + si[j];
        float tv = tanhf(sk[j]);
        float v = Xmid[(size_t)orig * 128 + f] * tv;
        Xpool[(size_t)(g * k + j) * 128 + f] = v;
        mx = fmaxf(mx, v);
        sm += v;
    }
    smx[t] = mx; ssm[t] = sm;
    __syncthreads();
    if (c == 0) {
        #pragma unroll
        for (int cc = 1; cc < 4; cc++) {
            mx = fmaxf(mx, smx[cc * 128 + f]);
            sm += ssm[cc * 128 + f];
        }
        float o1 = mx, o2 = sm / (float)k;
        if (accum) { r[g * 256 + f] += o1; r[g * 256 + 128 + f] += o2; }
        else       { r[g * 256 + f]  = o1; r[g * 256 + 128 + f]  = o2; }
    }
}

__global__ void k_compact(const int* __restrict__ srcI, const int* __restrict__ dstI,
                          const int* __restrict__ nmap, int* __restrict__ srcO,
                          int* __restrict__ dstO, int* __restrict__ cntOut,
                          const int* __restrict__ cntp, int cntv) {
    int n = cntp ? *cntp : cntv;
    int e = blockIdx.x * blockDim.x + threadIdx.x;
    if (e >= n) return;
    int ns = nmap[srcI[e]], nd = nmap[dstI[e]];
    if (ns >= 0 && nd >= 0) {
        int p = atomicAdd(cntOut, 1);
        srcO[p] = ns;
        dstO[p] = nd;
    }
}

__global__ void k_mlp(const float* __restrict__ r,
                      const float* __restrict__ l1W, const float* __restrict__ l1b,
                      const float* __restrict__ l2W, const float* __restrict__ l2b,
                      const float* __restrict__ l3W, const float* __restrict__ l3b,
                      float* __restrict__ out) {
    __shared__ float z0[256], z1[128], z2[64], z3[16];
    __shared__ float red2[2];
    int g = blockIdx.x, t = threadIdx.x;
    z0[t] = r[g * 256 + t];
    z0[t + 128] = r[g * 256 + 128 + t];
    __syncthreads();
    {
        float acc = l1b[t];
        for (int i = 0; i < 256; i++) acc = fmaf(z0[i], l1W[i * 128 + t], acc);
        z1[t] = fmaxf(acc, 0.f);
    }
    __syncthreads();
    if (t < 64) {
        float acc = l2b[t];
        for (int i = 0; i < 128; i++) acc = fmaf(z1[i], l2W[i * 64 + t], acc);
        z2[t] = fmaxf(acc, 0.f);
    }
    __syncthreads();
    if (t < NC) {
        float acc = l3b[t];
        for (int i = 0; i < 64; i++) acc = fmaf(z2[i], l3W[i * NC + t], acc);
        z3[t] = acc;
    }
    __syncthreads();
    if (t == 0) {
        float m = -FLT_MAX;
        for (int c = 0; c < NC; c++) m = fmaxf(m, z3[c]);
        float s = 0.f;
        for (int c = 0; c < NC; c++) s += expf(z3[c] - m);
        red2[0] = m; red2[1] = logf(s);
    }
    __syncthreads();
    if (t < NC) out[g * NC + t] = z3[t] - red2[0] - red2[1];
}

// ---------------- host side ----------------
struct Ptrs {
    float *X, *X2, *XS, *dinv, *catd, *r;
    int *nmap, *cnt0, *cnt1, *cnt2, *csr;
    int *srcA, *dstA, *srcB, *dstB, *ecnt;
};

static void run_stage(const Ptrs& P, const float* Xin, int* cnt, int n, int k,
                      const int* src, const int* dst, const int* cntp,
                      const float* W, const float* b, const float* A,
                      const float* psW, const float* psb,
                      float* Xpool, int accum,
                      bool doCompact, int* srcO, int* dstO, int* cntOut) {
    int nper = n / BGR;
    int egrid = ceil_div(NE, 256);
    k_build<<<egrid, 256>>>(src, dst, cnt, P.csr, cntp, NE);
    k_dinv<<<ceil_div(n, 256), 256>>>(cnt, P.dinv, n);
    k_scale<<<ceil_div(n * 32, 256), 256>>>(Xin, P.dinv, P.XS, n);
    k_aggXP<<<ceil_div(n, NPB3), 256>>>(P.XS, cnt, P.csr, P.dinv,
                                        W, b, A, psW, P.X, P.catd, n);
    k_select<<<BGR, 512>>>(P.catd, P.dinv, cnt, P.csr, psb,
                           P.X, P.nmap, Xpool, P.r, nper, k, accum);
    if (doCompact)
        k_compact<<<egrid, 256>>>(src, dst, P.nmap, srcO, dstO, cntOut, cntp, NE);
}

extern "C" void kernel_launch(void* const* d_in, const int* in_sizes, int n_in,
                              void* d_out, int out_size) {
    const float* x   = (const float*)d_in[0];
    const int*   src = (const int*)d_in[1];
    const int*   dst = (const int*)d_in[2];
    const float* W1 = (const float*)d_in[3];
    const float* b1 = (const float*)d_in[4];
    const float* A1 = (const float*)d_in[5];
    const float* ps1W = (const float*)d_in[6];
    const float* ps1b = (const float*)d_in[7];
    const float* W2 = (const float*)d_in[8];
    const float* b2 = (const float*)d_in[9];
    const float* A2 = (const float*)d_in[10];
    const float* ps2W = (const float*)d_in[11];
    const float* ps2b = (const float*)d_in[12];
    const float* W3 = (const float*)d_in[13];
    const float* b3 = (const float*)d_in[14];
    const float* A3 = (const float*)d_in[15];
    const float* ps3W = (const float*)d_in[16];
    const float* ps3b = (const float*)d_in[17];
    const float* l1W = (const float*)d_in[18];
    const float* l1b = (const float*)d_in[19];
    const float* l2W = (const float*)d_in[20];
    const float* l2b = (const float*)d_in[21];
    const float* l3W = (const float*)d_in[22];
    const float* l3b = (const float*)d_in[23];
    float* out = (float*)d_out;

    Ptrs P;
    cudaGetSymbolAddress((void**)&P.X, g_X);
    cudaGetSymbolAddress((void**)&P.X2, g_X2);
    cudaGetSymbolAddress((void**)&P.XS, g_XS);
    cudaGetSymbolAddress((void**)&P.dinv, g_dinv);
    cudaGetSymbolAddress((void**)&P.catd, g_catd);
    cudaGetSymbolAddress((void**)&P.r, g_r);
    cudaGetSymbolAddress((void**)&P.nmap, g_nmap);
    cudaGetSymbolAddress((void**)&P.cnt0, g_cnt0);
    cudaGetSymbolAddress((void**)&P.cnt1, g_cnt1);
    cudaGetSymbolAddress((void**)&P.cnt2, g_cnt2);
    cudaGetSymbolAddress((void**)&P.csr, g_csr);
    cudaGetSymbolAddress((void**)&P.srcA, g_srcA);
    cudaGetSymbolAddress((void**)&P.dstA, g_dstA);
    cudaGetSymbolAddress((void**)&P.srcB, g_srcB);
    cudaGetSymbolAddress((void**)&P.dstB, g_dstB);
    cudaGetSymbolAddress((void**)&P.ecnt, g_ecnt);

    k_init<<<ceil_div(N0, 256), 256>>>(P.cnt0, P.cnt1, P.cnt2, P.ecnt);

    run_stage(P, x, P.cnt0, N0, KK1, src, dst, nullptr,
              W1, b1, A1, ps1W, ps1b, P.X2, 0,
              true, P.srcA, P.dstA, &P.ecnt[0]);
    run_stage(P, P.X2, P.cnt1, N1, KK2, P.srcA, P.dstA, &P.ecnt[0],
              W2, b2, A2, ps2W, ps2b, P.X2, 1,
              true, P.srcB, P.dstB, &P.ecnt[1]);
    run_stage(P, P.X2, P.cnt2, N2, KK3, P.srcB, P.dstB, &P.ecnt[1],
              W3, b3, A3, ps3W, ps3b, P.X2, 1,
              false, nullptr, nullptr, nullptr);

    k_mlp<<<BGR, 128>>>(P.r, l1W, l1b, l2W, l2b, l3W, l3b, out);
}

// round 7
// speedup vs baseline: 1.3441x; 1.0003x over previous
#include <cuda_runtime.h>
#include <cuda_bf16.h>
#include <math.h>
#include <float.h>

#define BGR   32
#define NPER0 1024
#define N0    (BGR * NPER0)
#define HID   128
#define NE    524288
#define KK1   512
#define KK2   256
#define KK3   128
#define NC    10
#define MAXDEG 128
#define N1    (BGR * KK1)
#define N2    (BGR * KK2)

// ---------------- scratch (static device memory) ----------------
__device__ __align__(16) float g_X[N0 * HID];
__device__ __align__(16) float g_X2[N0 * HID];
__device__ __align__(16) float g_XS[N0 * HID];
__device__ float g_dinv[N0];
__device__ float g_catd[N0];
__device__ int   g_nmap[N0];
__device__ int   g_cnt0[N0];
__device__ int   g_cnt1[N1];
__device__ int   g_cnt2[N2];
__device__ int   g_csr[N0 * MAXDEG];
__device__ int   g_srcA[NE], g_dstA[NE];
__device__ int   g_srcB[NE], g_dstB[NE];
__device__ int   g_ecnt[2];
__device__ float g_r[BGR * 2 * HID];

static inline int ceil_div(int a, int b) { return (a + b - 1) / b; }

// order-preserving float->uint mapping (monotone increasing)
__device__ __forceinline__ unsigned f2u_ord(float f) {
    unsigned u = __float_as_uint(f);
    return (u & 0x80000000u) ? ~u : (u | 0x80000000u);
}
__device__ __forceinline__ float u2f_ord(unsigned m) {
    unsigned u = (m & 0x80000000u) ? (m & 0x7FFFFFFFu) : ~m;
    return __uint_as_float(u);
}

// ---------------- kernels ----------------
__global__ void k_init(int* c0, int* c1, int* c2, int* ecnt) {
    int i = blockIdx.x * blockDim.x + threadIdx.x;
    if (i < N0) c0[i] = 0;
    if (i < N1) c1[i] = 0;
    if (i < N2) c2[i] = 0;
    if (i < 2)  ecnt[i] = 0;
}

__global__ void k_build(const int* __restrict__ src, const int* __restrict__ dst,
                        int* __restrict__ cnt, int* __restrict__ csr,
                        const int* __restrict__ cntp, int cntv) {
    int n = cntp ? *cntp : cntv;
    int e = blockIdx.x * blockDim.x + threadIdx.x;
    if (e >= n) return;
    int d = dst[e];
    int slot = atomicAdd(&cnt[d], 1);
    if (slot < MAXDEG) csr[d * MAXDEG + slot] = src[e];
}

__global__ void k_dinv(const int* __restrict__ cnt, float* __restrict__ dinv, int n) {
    int i = blockIdx.x * blockDim.x + threadIdx.x;
    if (i >= n) return;
    dinv[i] = rsqrtf((float)(cnt[i] + 1));
}

__global__ void k_scale(const float* __restrict__ Xin, const float* __restrict__ dinv,
                        float* __restrict__ Xs, int n) {
    int i = blockIdx.x * blockDim.x + threadIdx.x;
    if (i >= n * 32) return;
    float4 v = ((const float4*)Xin)[i];
    float d = dinv[i >> 5];
    ((float4*)Xs)[i] = make_float4(v.x * d, v.y * d, v.z * d, v.w * d);
}

// Warp-per-node fused kernel (see R6 comments).
#define NPB3 32
__global__ void k_aggXP(const float* __restrict__ Xs, const int* __restrict__ cnt,
                        const int* __restrict__ csr, const float* __restrict__ dinv,
                        const float* __restrict__ W, const float* __restrict__ b,
                        const float* __restrict__ A, const float* __restrict__ psW,
                        float* __restrict__ Xout, float* __restrict__ catd, int n) {
    __shared__ float sW[4096];
    int t = threadIdx.x;
    #pragma unroll
    for (int i = 0; i < 16; i++) sW[i * 256 + t] = W[i * 256 + t];
    __syncthreads();
    int w = t >> 5, lane = t & 31;
    int head = lane >> 3;
    int baseLane = head << 3;
    int oct = lane & 7;
    const float4* Xs4 = (const float4*)Xs;
    float4 b4  = ((const float4*)b)[lane];
    float4 A4  = ((const float4*)A)[lane];
    float4 pw4 = ((const float4*)psW)[lane];
    const float* whBase = sW + head * 1024 + oct * 4;
    int base = blockIdx.x * NPB3;
    #pragma unroll 1
    for (int it = 0; it < NPB3 / 8; it++) {
        int node = base + it * 8 + w;
        if (node >= n) break;
        int deg = cnt[node];
        float di = dinv[node];
        const int* row = csr + (size_t)node * MAXDEG;
        float4 acc = Xs4[(size_t)node * 32 + lane];
        int j = 0;
        for (; j + 4 <= deg; j += 4) {
            int4 s4 = *(const int4*)(row + j);
            float4 v0 = Xs4[(size_t)s4.x * 32 + lane];
            float4 v1 = Xs4[(size_t)s4.y * 32 + lane];
            float4 v2 = Xs4[(size_t)s4.z * 32 + lane];
            float4 v3 = Xs4[(size_t)s4.w * 32 + lane];
            acc.x += (v0.x + v1.x) + (v2.x + v3.x);
            acc.y += (v0.y + v1.y) + (v2.y + v3.y);
            acc.z += (v0.z + v1.z) + (v2.z + v3.z);
            acc.w += (v0.w + v1.w) + (v2.w + v3.w);
        }
        for (; j < deg; j++) {
            float4 v0 = Xs4[(size_t)row[j] * 32 + lane];
            acc.x += v0.x; acc.y += v0.y; acc.z += v0.z; acc.w += v0.w;
        }
        float4 v = make_float4(acc.x * di, acc.y * di, acc.z * di, acc.w * di);
        float4 o = make_float4(0.f, 0.f, 0.f, 0.f);
        #pragma unroll
        for (int i = 0; i < 8; i++) {
            int sl = baseLane + i;
            float vv0 = __shfl_sync(0xffffffffu, v.x, sl);
            float vv1 = __shfl_sync(0xffffffffu, v.y, sl);
            float vv2 = __shfl_sync(0xffffffffu, v.z, sl);
            float vv3 = __shfl_sync(0xffffffffu, v.w, sl);
            const float* wp = whBase + (i * 4) * 32;
            float4 w0 = *(const float4*)(wp);
            float4 w1 = *(const float4*)(wp + 32);
            float4 w2 = *(const float4*)(wp + 64);
            float4 w3 = *(const float4*)(wp + 96);
            o.x = fmaf(vv0, w0.x, o.x); o.y = fmaf(vv0, w0.y, o.y);
            o.z = fmaf(vv0, w0.z, o.z); o.w = fmaf(vv0, w0.w, o.w);
            o.x = fmaf(vv1, w1.x, o.x); o.y = fmaf(vv1, w1.y, o.y);
            o.z = fmaf(vv1, w1.z, o.z); o.w = fmaf(vv1, w1.w, o.w);
            o.x = fmaf(vv2, w2.x, o.x); o.y = fmaf(vv2, w2.y, o.y);
            o.z = fmaf(vv2, w2.z, o.z); o.w = fmaf(vv2, w2.w, o.w);
            o.x = fmaf(vv3, w3.x, o.x); o.y = fmaf(vv3, w3.y, o.y);
            o.z = fmaf(vv3, w3.z, o.z); o.w = fmaf(vv3, w3.w, o.w);
        }
        o.x = fmaxf(o.x + b4.x, 0.f);
        o.y = fmaxf(o.y + b4.y, 0.f);
        o.z = fmaxf(o.z + b4.z, 0.f);
        o.w = fmaxf(o.w + b4.w, 0.f);
        ((float4*)Xout)[(size_t)node * 32 + lane] = o;
        float att = o.x * A4.x + o.y * A4.y + o.z * A4.z + o.w * A4.w;
        att += __shfl_xor_sync(0xffffffffu, att, 1);
        att += __shfl_xor_sync(0xffffffffu, att, 2);
        att += __shfl_xor_sync(0xffffffffu, att, 4);
        float cp = att * (o.x * pw4.x + o.y * pw4.y + o.z * pw4.z + o.w * pw4.w);
        #pragma unroll
        for (int ofs = 16; ofs > 0; ofs >>= 1)
            cp += __shfl_xor_sync(0xffffffffu, cp, ofs);
        if (lane == 0) catd[node] = cp * di;
    }
}

// Fused per-graph select: score gather, packed-u64 bitonic sort, nmap, pool+readout.
__global__ void k_select(const float* __restrict__ catd, const float* __restrict__ dinv,
                         const int* __restrict__ cnt, const int* __restrict__ csr,
                         const float* __restrict__ psb, const float* __restrict__ Xmid,
                         int* __restrict__ nmap, float* __restrict__ Xpool,
                         float* __restrict__ r, int nper, int k, int accum) {
    __shared__ unsigned long long skey[1024];
    __shared__ float scd[1024];
    __shared__ float smx[512], ssm[512];
    int g = blockIdx.x, t = threadIdx.x;   // 512 threads
    int base = g * nper;
    for (int i = t; i < nper; i += 512) {
        int node = base + i;
        scd[i] = catd[node];
        nmap[node] = -1;
    }
    __syncthreads();
    float pb = psb[0];
    for (int i = t; i < nper; i += 512) {
        int node = base + i;
        int deg = cnt[node];
        const int* row = csr + (size_t)node * MAXDEG;
        float din = dinv[node];
        float s2 = scd[i] * din;
        for (int j = 0; j < deg; j++) s2 += scd[row[j] - base];
        float sc = fmaf(s2, din, pb);
        // pack: hi = order bits (desc sort => larger first), lo = ~i (lower idx wins)
        skey[i] = ((unsigned long long)f2u_ord(sc) << 32) | (unsigned)(~i);
    }
    __syncthreads();
    for (int ks = 2; ks <= nper; ks <<= 1) {
        for (int j = ks >> 1; j > 0; j >>= 1) {
            for (int i = t; i < nper; i += 512) {
                int ixj = i ^ j;
                if (ixj > i) {
                    unsigned long long ka = skey[i], kb = skey[ixj];
                    bool dirUp = ((i & ks) == 0);     // descending
                    bool sw = dirUp ? (ka < kb) : (ka > kb);
                    if (sw) { skey[i] = kb; skey[ixj] = ka; }
                }
            }
            __syncthreads();
        }
    }
    for (int jj = t; jj < k; jj += 512)
        nmap[base + (int)(~(unsigned)skey[jj])] = g * k + jj;
    int f = t & 127, c = t >> 7;
    float mx = -FLT_MAX, sm = 0.f;
    for (int j = c; j < k; j += 4) {
        unsigned long long key = skey[j];
        int orig = base + (int)(~(unsigned)key);
        float tv = tanhf(u2f_ord((unsigned)(key >> 32)));
        float v = Xmid[(size_t)orig * 128 + f] * tv;
        Xpool[(size_t)(g * k + j) * 128 + f] = v;
        mx = fmaxf(mx, v);
        sm += v;
    }
    smx[t] = mx; ssm[t] = sm;
    __syncthreads();
    if (c == 0) {
        #pragma unroll
        for (int cc = 1; cc < 4; cc++) {
            mx = fmaxf(mx, smx[cc * 128 + f]);
            sm += ssm[cc * 128 + f];
        }
        float o1 = mx, o2 = sm / (float)k;
        if (accum) { r[g * 256 + f] += o1; r[g * 256 + 128 + f] += o2; }
        else       { r[g * 256 + f]  = o1; r[g * 256 + 128 + f]  = o2; }
    }
}

// warp-aggregated compaction: 1 atomic per warp instead of per edge
__global__ void k_compact(const int* __restrict__ srcI, const int* __restrict__ dstI,
                          const int* __restrict__ nmap, int* __restrict__ srcO,
                          int* __restrict__ dstO, int* __restrict__ cntOut,
                          const int* __restrict__ cntp, int cntv) {
    int n = cntp ? *cntp : cntv;
    int e = blockIdx.x * blockDim.x + threadIdx.x;
    int lane = threadIdx.x & 31;
    int ns = -1, nd = -1;
    bool keep = false;
    if (e < n) {
        ns = nmap[srcI[e]];
        nd = nmap[dstI[e]];
        keep = (ns >= 0 && nd >= 0);
    }
    unsigned m = __ballot_sync(0xffffffffu, keep);
    if (m == 0) return;
    int cnt = __popc(m);
    int leader = __ffs(m) - 1;
    int basep = 0;
    if (lane == leader) basep = atomicAdd(cntOut, cnt);
    basep = __shfl_sync(0xffffffffu, basep, leader);
    if (keep) {
        int off = __popc(m & ((1u << lane) - 1u));
        srcO[basep + off] = ns;
        dstO[basep + off] = nd;
    }
}

__global__ void k_mlp(const float* __restrict__ r,
                      const float* __restrict__ l1W, const float* __restrict__ l1b,
                      const float* __restrict__ l2W, const float* __restrict__ l2b,
                      const float* __restrict__ l3W, const float* __restrict__ l3b,
                      float* __restrict__ out) {
    __shared__ float z0[256], z1[128], z2[64], z3[16];
    __shared__ float red2[2];
    int g = blockIdx.x, t = threadIdx.x;
    z0[t] = r[g * 256 + t];
    z0[t + 128] = r[g * 256 + 128 + t];
    __syncthreads();
    {
        float acc = l1b[t];
        for (int i = 0; i < 256; i++) acc = fmaf(z0[i], l1W[i * 128 + t], acc);
        z1[t] = fmaxf(acc, 0.f);
    }
    __syncthreads();
    if (t < 64) {
        float acc = l2b[t];
        for (int i = 0; i < 128; i++) acc = fmaf(z1[i], l2W[i * 64 + t], acc);
        z2[t] = fmaxf(acc, 0.f);
    }
    __syncthreads();
    if (t < NC) {
        float acc = l3b[t];
        for (int i = 0; i < 64; i++) acc = fmaf(z2[i], l3W[i * NC + t], acc);
        z3[t] = acc;
    }
    __syncthreads();
    if (t == 0) {
        float m = -FLT_MAX;
        for (int c = 0; c < NC; c++) m = fmaxf(m, z3[c]);
        float s = 0.f;
        for (int c = 0; c < NC; c++) s += expf(z3[c] - m);
        red2[0] = m; red2[1] = logf(s);
    }
    __syncthreads();
    if (t < NC) out[g * NC + t] = z3[t] - red2[0] - red2[1];
}

// ---------------- host side ----------------
struct Ptrs {
    float *X, *X2, *XS, *dinv, *catd, *r;
    int *nmap, *cnt0, *cnt1, *cnt2, *csr;
    int *srcA, *dstA, *srcB, *dstB, *ecnt;
};

static void run_stage(const Ptrs& P, const float* Xin, int* cnt, int n, int k,
                      const int* src, const int* dst, const int* cntp,
                      const float* W, const float* b, const float* A,
                      const float* psW, const float* psb,
                      float* Xpool, int accum,
                      bool doCompact, int* srcO, int* dstO, int* cntOut) {
    int nper = n / BGR;
    int egrid = ceil_div(NE, 256);
    k_build<<<egrid, 256>>>(src, dst, cnt, P.csr, cntp, NE);
    k_dinv<<<ceil_div(n, 256), 256>>>(cnt, P.dinv, n);
    k_scale<<<ceil_div(n * 32, 256), 256>>>(Xin, P.dinv, P.XS, n);
    k_aggXP<<<ceil_div(n, NPB3), 256>>>(P.XS, cnt, P.csr, P.dinv,
                                        W, b, A, psW, P.X, P.catd, n);
    k_select<<<BGR, 512>>>(P.catd, P.dinv, cnt, P.csr, psb,
                           P.X, P.nmap, Xpool, P.r, nper, k, accum);
    if (doCompact)
        k_compact<<<egrid, 256>>>(src, dst, P.nmap, srcO, dstO, cntOut, cntp, NE);
}

extern "C" void kernel_launch(void* const* d_in, const int* in_sizes, int n_in,
                              void* d_out, int out_size) {
    const float* x   = (const float*)d_in[0];
    const int*   src = (const int*)d_in[1];
    const int*   dst = (const int*)d_in[2];
    const float* W1 = (const float*)d_in[3];
    const float* b1 = (const float*)d_in[4];
    const float* A1 = (const float*)d_in[5];
    const float* ps1W = (const float*)d_in[6];
    const float* ps1b = (const float*)d_in[7];
    const float* W2 = (const float*)d_in[8];
    const float* b2 = (const float*)d_in[9];
    const float* A2 = (const float*)d_in[10];
    const float* ps2W = (const float*)d_in[11];
    const float* ps2b = (const float*)d_in[12];
    const float* W3 = (const float*)d_in[13];
    const float* b3 = (const float*)d_in[14];
    const float* A3 = (const float*)d_in[15];
    const float* ps3W = (const float*)d_in[16];
    const float* ps3b = (const float*)d_in[17];
    const float* l1W = (const float*)d_in[18];
    const float* l1b = (const float*)d_in[19];
    const float* l2W = (const float*)d_in[20];
    const float* l2b = (const float*)d_in[21];
    const float* l3W = (const float*)d_in[22];
    const float* l3b = (const float*)d_in[23];
    float* out = (float*)d_out;

    Ptrs P;
    cudaGetSymbolAddress((void**)&P.X, g_X);
    cudaGetSymbolAddress((void**)&P.X2, g_X2);
    cudaGetSymbolAddress((void**)&P.XS, g_XS);
    cudaGetSymbolAddress((void**)&P.dinv, g_dinv);
    cudaGetSymbolAddress((void**)&P.catd, g_catd);
    cudaGetSymbolAddress((void**)&P.r, g_r);
    cudaGetSymbolAddress((void**)&P.nmap, g_nmap);
    cudaGetSymbolAddress((void**)&P.cnt0, g_cnt0);
    cudaGetSymbolAddress((void**)&P.cnt1, g_cnt1);
    cudaGetSymbolAddress((void**)&P.cnt2, g_cnt2);
    cudaGetSymbolAddress((void**)&P.csr, g_csr);
    cudaGetSymbolAddress((void**)&P.srcA, g_srcA);
    cudaGetSymbolAddress((void**)&P.dstA, g_dstA);
    cudaGetSymbolAddress((void**)&P.srcB, g_srcB);
    cudaGetSymbolAddress((void**)&P.dstB, g_dstB);
    cudaGetSymbolAddress((void**)&P.ecnt, g_ecnt);

    k_init<<<ceil_div(N0, 256), 256>>>(P.cnt0, P.cnt1, P.cnt2, P.ecnt);

    run_stage(P, x, P.cnt0, N0, KK1, src, dst, nullptr,
              W1, b1, A1, ps1W, ps1b, P.X2, 0,
              true, P.srcA, P.dstA, &P.ecnt[0]);
    run_stage(P, P.X2, P.cnt1, N1, KK2, P.srcA, P.dstA, &P.ecnt[0],
              W2, b2, A2, ps2W, ps2b, P.X2, 1,
              true, P.srcB, P.dstB, &P.ecnt[1]);
    run_stage(P, P.X2, P.cnt2, N2, KK3, P.srcB, P.dstB, &P.ecnt[1],
              W3, b3, A3, ps3W, ps3b, P.X2, 1,
              false, nullptr, nullptr, nullptr);

    k_mlp<<<BGR, 128>>>(P.r, l1W, l1b, l2W, l2b, l3W, l3b, out);
}